// round 3
// baseline (speedup 1.0000x reference)
#include <cuda_runtime.h>
#include <cuda_bf16.h>

#define OUT_CH 128

// One warp per edge. segment_ids are globally sorted, so edge e's tokens are
// the contiguous range [lower_bound(segs, e), lower_bound(segs, e+1)).
//
// Latency optimizations vs v1:
//  - 32-ary warp-parallel lower_bound: 6 ballot rounds instead of 21 serial probes
//  - both lower_bounds (e and e+1) interleaved in one loop: chains overlap
//  - int4 token loads + packed 16-bit counters (1 shift-add per token)
__global__ void __launch_bounds__(256)
edge_mean_kernel(const int* __restrict__ tokens,
                 const int* __restrict__ segs,
                 const float* __restrict__ emb,   // [4][128]
                 float* __restrict__ out,         // [E][128]
                 int total_tokens,
                 int n_edges) {
    const int warp_id = (blockIdx.x * blockDim.x + threadIdx.x) >> 5;
    const int lane    = threadIdx.x & 31;
    if (warp_id >= n_edges) return;
    const int e = warp_id;

    // ---- interleaved warp-parallel lower_bound for e and e+1 ----
    // Invariant: lower_bound(v) ∈ [lo, hi].
    int lo0 = 0, hi0 = total_tokens;   // searching value e
    int lo1 = 0, hi1 = total_tokens;   // searching value e+1

    while ((hi0 > lo0) | (hi1 > lo1)) {
        int v0 = 0x7FFFFFFF, v1 = 0x7FFFFFFF;
        int step0 = 0, step1 = 0;
        if (hi0 > lo0) {
            step0 = (hi0 - lo0 + 31) >> 5;        // ceil(range/32)
            int idx = lo0 + lane * step0;
            if (idx < hi0) v0 = __ldg(&segs[idx]);
        }
        if (hi1 > lo1) {
            step1 = (hi1 - lo1 + 31) >> 5;
            int idx = lo1 + lane * step1;
            if (idx < hi1) v1 = __ldg(&segs[idx]);
        }
        if (hi0 > lo0) {
            unsigned m = __ballot_sync(0xFFFFFFFFu, v0 < e);
            int cnt = __popc(m);                  // probes are sorted -> contiguous mask
            int nlo = cnt ? lo0 + (cnt - 1) * step0 + 1 : lo0;
            int nhi = (cnt < 32) ? min(hi0, lo0 + cnt * step0) : hi0;
            lo0 = nlo; hi0 = max(nhi, nlo);
        }
        if (hi1 > lo1) {
            unsigned m = __ballot_sync(0xFFFFFFFFu, v1 < e + 1);
            int cnt = __popc(m);
            int nlo = cnt ? lo1 + (cnt - 1) * step1 + 1 : lo1;
            int nhi = (cnt < 32) ? min(hi1, lo1 + cnt * step1) : hi1;
            lo1 = nlo; hi1 = max(nhi, nlo);
        }
    }
    const int start = lo0;
    const int end   = lo1;

    // ---- count the 4 token values over [start, end) with int4 loads ----
    // acc packs counts of token t in 16-bit field t of a u64.
    const int4* tokens4 = (const int4*)tokens;
    const int s4 = start >> 2;
    const int e4 = (end + 3) >> 2;

    unsigned long long acc = 0ull;
    for (int j = s4 + lane; j < e4; j += 32) {
        int4 v = tokens4[j];
        int bi = j << 2;
        if (bi >= start && bi + 3 < end) {        // fast interior path
            acc += (1ull << (v.x * 16)) + (1ull << (v.y * 16))
                 + (1ull << (v.z * 16)) + (1ull << (v.w * 16));
        } else {                                   // boundary int4
            if (bi + 0 >= start && bi + 0 < end) acc += 1ull << (v.x * 16);
            if (bi + 1 >= start && bi + 1 < end) acc += 1ull << (v.y * 16);
            if (bi + 2 >= start && bi + 2 < end) acc += 1ull << (v.z * 16);
            if (bi + 3 >= start && bi + 3 < end) acc += 1ull << (v.w * 16);
        }
    }
    // Field totals <= segment length (~350) << 65536: no cross-field carry.
    unsigned lo32 = __reduce_add_sync(0xFFFFFFFFu, (unsigned)acc);
    unsigned hi32 = __reduce_add_sync(0xFFFFFFFFu, (unsigned)(acc >> 32));

    const float f0 = (float)(lo32 & 0xFFFFu);
    const float f1 = (float)(lo32 >> 16);
    const float f2 = (float)(hi32 & 0xFFFFu);
    const float f3 = (float)(hi32 >> 16);
    const float inv = 1.0f / fmaxf(f0 + f1 + f2 + f3, 1.0f);

    // ---- epilogue: 4 channels per lane, one float4 store ----
    const int d = lane * 4;
    const float4 e0 = *(const float4*)(emb + 0 * OUT_CH + d);
    const float4 e1 = *(const float4*)(emb + 1 * OUT_CH + d);
    const float4 e2 = *(const float4*)(emb + 2 * OUT_CH + d);
    const float4 e3 = *(const float4*)(emb + 3 * OUT_CH + d);

    float4 r;
    r.x = (f0 * e0.x + f1 * e1.x + f2 * e2.x + f3 * e3.x) * inv;
    r.y = (f0 * e0.y + f1 * e1.y + f2 * e2.y + f3 * e3.y) * inv;
    r.z = (f0 * e0.z + f1 * e1.z + f2 * e2.z + f3 * e3.z) * inv;
    r.w = (f0 * e0.w + f1 * e1.w + f2 * e2.w + f3 * e3.w) * inv;

    *(float4*)(out + (long long)e * OUT_CH + d) = r;
}

extern "C" void kernel_launch(void* const* d_in, const int* in_sizes, int n_in,
                              void* d_out, int out_size) {
    // Inputs: 0 overlap_similarity f32[E], 1 overlap_length f32[E],
    //         2 tokens i32[T], 3 segment_ids i32[T], 4 embedding f32[4*128],
    //         5 n_edges
    const int*   tokens = (const int*)d_in[2];
    const int*   segs   = (const int*)d_in[3];
    const float* emb    = (const float*)d_in[4];
    float*       out    = (float*)d_out;

    const int total_tokens = in_sizes[2];
    const int n_edges      = out_size / OUT_CH;

    const int threads = 256;                    // 8 warps -> 8 edges per block
    const int blocks  = (n_edges * 32 + threads - 1) / threads;
    edge_mean_kernel<<<blocks, threads>>>(tokens, segs, emb, out,
                                          total_tokens, n_edges);
}